// round 13
// baseline (speedup 1.0000x reference)
#include <cuda_runtime.h>
#include <math_constants.h>

#define Bsz 2048
#define Dd 16
#define Ff 512
#define LOG2E_F 1.4426950408889634f
#define LN2_F 0.6931471805599453f
#define LOG2PI_F 1.8378770664093453f

#define NPAIR 384            // 128 rowgroups x 3 j-thirds
#define NRECON 60            // recon blocks
#define NGRID (NPAIR + NRECON)   // 444 = 148 SM x 3 CTA: exactly one wave

typedef unsigned long long ull;

// Coefficient store: segment s = dp*3 + type (dp=dim-pair 0..7, type a/b/c),
// each segment is float2[2048] over j: float2[j] = {coef_{2dp}[j], coef_{2dp+1}[j]}
__device__ float g_pk2f[24 * 2048 * 2];   // 393 KB
__device__ float g_arr0[Bsz];             // log q(z|x) - log p(z)
__device__ float g_ph[3][Bsz * 20];       // per-third partials: 16 dim sums + srow (pad 20)
__device__ float g_comb[Bsz];             // arr0 + 3*ln2*(lg2 srow - sum lg2 s_d)
__device__ float g_part[NRECON];          // recon partials
__device__ unsigned g_rgc[128];           // per-rowgroup counters (monotonic, mod 3)
__device__ unsigned g_count;              // all-blocks counter (monotonic, mod NGRID)
__device__ unsigned g_sync;               // prep grid-barrier counter (monotonic)

__device__ __forceinline__ float ex2f(float x) {
    float y; asm("ex2.approx.ftz.f32 %0, %1;" : "=f"(y) : "f"(x)); return y;
}
__device__ __forceinline__ float lg2f_(float x) {
    float y; asm("lg2.approx.f32 %0, %1;" : "=f"(y) : "f"(x)); return y;
}
__device__ __forceinline__ ull fma2_(ull a, ull b, ull c) {
    ull d; asm("fma.rn.f32x2 %0, %1, %2, %3;" : "=l"(d) : "l"(a), "l"(b), "l"(c)); return d;
}
__device__ __forceinline__ ull add2_(ull a, ull b) {
    ull d; asm("add.rn.f32x2 %0, %1, %2;" : "=l"(d) : "l"(a), "l"(b)); return d;
}
__device__ __forceinline__ ull mul2_(ull a, ull b) {
    ull d; asm("mul.rn.f32x2 %0, %1, %2;" : "=l"(d) : "l"(a), "l"(b)); return d;
}
// exp2 of both halves of a packed f32x2, result packed
__device__ __forceinline__ ull ex2p_(ull u) {
    ull r;
    asm("{\n\t.reg .f32 l,h,a,b;\n\t"
        "mov.b64 {l,h}, %1;\n\t"
        "ex2.approx.ftz.f32 a, l;\n\t"
        "ex2.approx.ftz.f32 b, h;\n\t"
        "mov.b64 %0, {a,b};\n\t}" : "=l"(r) : "l"(u));
    return r;
}
__device__ __forceinline__ void unpk(ull v, float& lo, float& hi) {
    asm("mov.b64 {%0, %1}, %2;" : "=f"(lo), "=f"(hi) : "l"(v));
}
__device__ __forceinline__ ull pk2(float lo, float hi) {
    ull v; asm("mov.b64 %0, {%1, %2};" : "=l"(v) : "f"(lo), "f"(hi)); return v;
}
__device__ __forceinline__ void cpa16(unsigned d, const void* s) {
    asm volatile("cp.async.cg.shared.global [%0], [%1], 16;" :: "r"(d), "l"(s));
}

// ---------------------------------------------------------------------------
// Single persistent kernel, one wave (444 blocks x 256 threads, 3 CTAs/SM).
//  Phase 0: pairwise blocks 0..255 compute prep slices (coeffs + arr0), all
//    pairwise blocks then pass a monotonic grid barrier (recon don't spin).
//  Phase 1: b<384 pairwise (rowgroup x j-third, triple-buffered cp.async,
//           product-based row accumulation); b>=384 recon MAE partials.
//  Per-rowgroup third finisher (mod-3 counter) merges; last block overall
//  (mod-NGRID counter) does the final combine -> out[0].
// ---------------------------------------------------------------------------
__global__ void __launch_bounds__(256, 3) k_all(const float* __restrict__ mu,
                                                const float* __restrict__ lv,
                                                const float* __restrict__ z,
                                                const int* __restrict__ nds,
                                                const float* __restrict__ x,
                                                const float* __restrict__ rec,
                                                float* __restrict__ out) {
    __shared__ float4 sbuf[3][768];               // 3 x 12 KB tiles
    __shared__ float sred[256];
    __shared__ unsigned s_tmp;
    const int tid = threadIdx.x;
    const int lane = tid & 31;
    const int b = blockIdx.x;
    const ull ONE2 = 0x3F8000003F800000ull;       // {1.0f, 1.0f}

    if (b < NPAIR) {
        // ================= phase 0: prep slice =================
        if (b < 256) {
            if (tid < 128) {
                int idx = b * 128 + tid;          // 256*128 = 32768 = Bsz*Dd
                int j = idx >> 4, d = idx & 15;
                float m = mu[idx], v = lv[idx];
                float a = -0.5f * LOG2E_F * ex2f(-v * LOG2E_F);
                float off = -0.5f * LOG2E_F * (v + LOG2PI_F);
                float bb = -2.0f * a * m;
                float c = fmaf(a * m, m, off);
                if (j < 2) {
                    float Nf = (float)(*nds);
                    float dL0 = lg2f_(2047.0f / Nf);
                    float dL1 = lg2f_((Nf - 2047.0f) / Nf);
                    c += (j == 0) ? dL0 : dL1;
                }
                int dp = d >> 1, h = d & 1;
                int e = j * 2 + h;
                g_pk2f[(dp * 3 + 0) * 4096 + e] = a;
                g_pk2f[(dp * 3 + 1) * 4096 + e] = bb;
                g_pk2f[(dp * 3 + 2) * 4096 + e] = c;
            } else if (tid < 136) {
                int i = b * 8 + (tid - 128);      // 256*8 = 2048
                float acc = 0.f, sz2 = 0.f;
#pragma unroll
                for (int d = 0; d < Dd; d++) {
                    float zd = z[i * Dd + d];
                    float md = mu[i * Dd + d];
                    float vd = lv[i * Dd + d];
                    float t = zd - md;
                    acc += -0.5f * (t * t * ex2f(-vd * LOG2E_F) + vd + LOG2PI_F);
                    sz2 = fmaf(zd, zd, sz2);
                }
                float lprior = -0.5f * (sz2 * 0.36787944117144233f + 16.0f * (1.0f + LOG2PI_F));
                g_arr0[i] = acc - lprior;
            }
        }
        __threadfence();
        __syncthreads();
        if (tid == 0) {
            unsigned old = atomicAdd(&g_sync, 1u);
            unsigned target = (old / NGRID + 1u) * NGRID;
            while (*(volatile unsigned*)&g_sync < target) { }
        }
        __syncthreads();
        __threadfence();

        // ================= phase 1: pairwise =================
        const int third = b >> 7;                 // 0,1,2 (j-third)
        const int rg = b & 127;                   // row-group (16 rows)
        const int NT = (third < 2) ? 11 : 10;     // tiles in this third
        const int toff = third * 11;              // first tile (third 2 -> 22)
        const int w = tid >> 5;                   // 0..7
        const int i0 = rg * 16 + 2 * w, i1 = i0 + 1;

        ull zp0[8], zp1[8];
        {
            const float4* zq = (const float4*)(z + (size_t)i0 * Dd);
#pragma unroll
            for (int k = 0; k < 4; k++) {
                float4 v = zq[k];
                zp0[2 * k] = pk2(v.x, v.y); zp0[2 * k + 1] = pk2(v.z, v.w);
            }
            const float4* zq1 = (const float4*)(z + (size_t)i1 * Dd);
#pragma unroll
            for (int k = 0; k < 4; k++) {
                float4 v = zq1[k];
                zp1[2 * k] = pk2(v.x, v.y); zp1[2 * k + 1] = pk2(v.z, v.w);
            }
        }

        ull s20[8], s21[8];                       // packed per-dim sums
        float srow0 = 0.f, srow1 = 0.f;
#pragma unroll
        for (int dp = 0; dp < 8; dp++) { s20[dp] = 0ull; s21[dp] = 0ull; }

        // single-base addressing: chunk k at +k*131072 (src) / +k*4096 (dst)
        const char* srcbase = (const char*)g_pk2f
                            + ((size_t)(tid >> 5) * 1024 + (tid & 31)) * 16
                            + (size_t)toff * 512;
        const unsigned dstb0 = (unsigned)__cvta_generic_to_shared(&sbuf[0][0])
                             + (unsigned)(((tid >> 5) * 32 + (tid & 31)) * 16);

        // prologue: stage tiles 0 and 1 of this third
#pragma unroll
        for (int k = 0; k < 3; k++) cpa16(dstb0 + k * 4096u, srcbase + (size_t)k * 131072);
        asm volatile("cp.async.commit_group;");
#pragma unroll
        for (int k = 0; k < 3; k++) cpa16(dstb0 + 12288u + k * 4096u, srcbase + 512 + (size_t)k * 131072);
        asm volatile("cp.async.commit_group;");

        int rb = 0;   // t % 3
#pragma unroll 1
        for (int t = 0; t < NT; t++) {
            asm volatile("cp.async.wait_group 1;");
            __syncthreads();

            const ulonglong2* sb2 = (const ulonglong2*)sbuf[rb];
            ull P00 = ONE2, P01 = ONE2, P10 = ONE2, P11 = ONE2;

#pragma unroll
            for (int dp = 0; dp < 8; dp++) {
                ulonglong2 A = sb2[(dp * 3 + 0) * 32 + lane];
                ulonglong2 B = sb2[(dp * 3 + 1) * 32 + lane];
                ulonglong2 C = sb2[(dp * 3 + 2) * 32 + lane];
                ull u, e;
                u = fma2_(zp0[dp], fma2_(zp0[dp], A.x, B.x), C.x);
                e = ex2p_(u); s20[dp] = add2_(s20[dp], e); P00 = mul2_(P00, e);
                u = fma2_(zp0[dp], fma2_(zp0[dp], A.y, B.y), C.y);
                e = ex2p_(u); s20[dp] = add2_(s20[dp], e); P01 = mul2_(P01, e);
                u = fma2_(zp1[dp], fma2_(zp1[dp], A.x, B.x), C.x);
                e = ex2p_(u); s21[dp] = add2_(s21[dp], e); P10 = mul2_(P10, e);
                u = fma2_(zp1[dp], fma2_(zp1[dp], A.y, B.y), C.y);
                e = ex2p_(u); s21[dp] = add2_(s21[dp], e); P11 = mul2_(P11, e);
            }
            {   // row term = product over all 16 dims = l*h of packed product
                float l, h;
                unpk(P00, l, h); srow0 = fmaf(l, h, srow0);
                unpk(P01, l, h); srow0 = fmaf(l, h, srow0);
                unpk(P10, l, h); srow1 = fmaf(l, h, srow1);
                unpk(P11, l, h); srow1 = fmaf(l, h, srow1);
            }

            // fill tile t+2 into buf[(t+2)%3] (== buffer consumed at t-1; the
            // sync above proves all threads finished compute(t-1)).
            if (t + 2 < NT) {
                int fb = rb + 2; if (fb >= 3) fb -= 3;
                unsigned boff = (unsigned)fb * 12288u;
                const char* sp = srcbase + (size_t)(t + 2) * 512;
#pragma unroll
                for (int k = 0; k < 3; k++)
                    cpa16(dstb0 + boff + k * 4096u, sp + (size_t)k * 131072);
            }
            asm volatile("cp.async.commit_group;");
            if (++rb == 3) rb = 0;
        }

        // unpack packed accumulators
        float s0[16], s1[16];
#pragma unroll
        for (int dp = 0; dp < 8; dp++) {
            unpk(s20[dp], s0[2 * dp], s0[2 * dp + 1]);
            unpk(s21[dp], s1[2 * dp], s1[2 * dp + 1]);
        }

        // ---- post-loop exact corrections: j=0/1 live in third 0, lane 0 ----
        if (third == 0 && lane == 0) {
            const ulonglong2* pk = (const ulonglong2*)g_pk2f;
            float Nf = (float)(*nds);
            float dL0 = lg2f_(2047.0f / Nf);
            float dL1 = lg2f_((Nf - 2047.0f) / Nf);
            float S0_0 = 0.f, S1_0 = 0.f, S0_1 = 0.f, S1_1 = 0.f;
#pragma unroll
            for (int dp = 0; dp < 8; dp++) {
                ulonglong2 A = pk[(dp * 3 + 0) * 1024];
                ulonglong2 B = pk[(dp * 3 + 1) * 1024];
                ulonglong2 C = pk[(dp * 3 + 2) * 1024];
                float l, h;
                ull u0 = fma2_(zp0[dp], fma2_(zp0[dp], A.x, B.x), C.x);
                unpk(u0, l, h); S0_0 += l + h;
                ull u1 = fma2_(zp0[dp], fma2_(zp0[dp], A.y, B.y), C.y);
                unpk(u1, l, h); S1_0 += l + h;
                ull v0 = fma2_(zp1[dp], fma2_(zp1[dp], A.x, B.x), C.x);
                unpk(v0, l, h); S0_1 += l + h;
                ull v1 = fma2_(zp1[dp], fma2_(zp1[dp], A.y, B.y), C.y);
                unpk(v1, l, h); S1_1 += l + h;
            }
            // row-sum: loop applied 16*dL_j; true weight is 1*dL_j(row).
            float c00 = (i0 == Bsz - 2) ? (dL1 - 16.f * dL0) : (-15.f * dL0);
            float c01 = -15.f * dL0;                  // odd rows are never B-2
            float c1  = -15.f * dL1;
            srow0 += (ex2f(c00) - 1.f) * ex2f(S0_0) + (ex2f(c1) - 1.f) * ex2f(S1_0);
            srow1 += (ex2f(c01) - 1.f) * ex2f(S0_1) + (ex2f(c1) - 1.f) * ex2f(S1_1);
            // W[B-2, 0] per-dim override (row B-2 is even -> row i0): recompute u
            if (i0 == Bsz - 2) {
                float wfix = ex2f(dL1 - dL0) - 1.f;
#pragma unroll
                for (int dp = 0; dp < 8; dp++) {
                    ulonglong2 A = pk[(dp * 3 + 0) * 1024];
                    ulonglong2 B = pk[(dp * 3 + 1) * 1024];
                    ulonglong2 C = pk[(dp * 3 + 2) * 1024];
                    float l, h;
                    ull u0 = fma2_(zp0[dp], fma2_(zp0[dp], A.x, B.x), C.x);
                    unpk(u0, l, h);
                    s0[2 * dp] += wfix * ex2f(l);
                    s0[2 * dp + 1] += wfix * ex2f(h);
                }
            }
        }

        // ---- plain-sum butterfly ----
#pragma unroll
        for (int off = 16; off > 0; off >>= 1) {
#pragma unroll
            for (int d = 0; d < 16; d++) {
                s0[d] += __shfl_xor_sync(0xffffffffu, s0[d], off);
                s1[d] += __shfl_xor_sync(0xffffffffu, s1[d], off);
            }
            srow0 += __shfl_xor_sync(0xffffffffu, srow0, off);
            srow1 += __shfl_xor_sync(0xffffffffu, srow1, off);
        }

        // ---- write third partials ----
        if (lane == 0) {
            float* ph = &g_ph[third][0];
            float4* d0 = (float4*)&ph[i0 * 20];
            d0[0] = make_float4(s0[0], s0[1], s0[2], s0[3]);
            d0[1] = make_float4(s0[4], s0[5], s0[6], s0[7]);
            d0[2] = make_float4(s0[8], s0[9], s0[10], s0[11]);
            d0[3] = make_float4(s0[12], s0[13], s0[14], s0[15]);
            ph[i0 * 20 + 16] = srow0;
            float4* d1 = (float4*)&ph[i1 * 20];
            d1[0] = make_float4(s1[0], s1[1], s1[2], s1[3]);
            d1[1] = make_float4(s1[4], s1[5], s1[6], s1[7]);
            d1[2] = make_float4(s1[8], s1[9], s1[10], s1[11]);
            d1[3] = make_float4(s1[12], s1[13], s1[14], s1[15]);
            ph[i1 * 20 + 16] = srow1;
        }
        __syncthreads();
        if (tid == 0) {
            __threadfence();
            s_tmp = atomicAdd(&g_rgc[rg], 1u);
        }
        __syncthreads();
        if (s_tmp % 3u == 2u) {      // last finisher of this rowgroup merges
            __threadfence();
            if (lane == 0) {
                const float* p0 = &g_ph[0][i0 * 20];
                const float* p1 = &g_ph[1][i0 * 20];
                const float* p2 = &g_ph[2][i0 * 20];
                float acc = 0.f;
#pragma unroll
                for (int d = 0; d < 16; d++) acc += lg2f_(p0[d] + p1[d] + p2[d]);
                g_comb[i0] = g_arr0[i0]
                           + 3.f * LN2_F * (lg2f_(p0[16] + p1[16] + p2[16]) - acc);
                p0 = &g_ph[0][i1 * 20]; p1 = &g_ph[1][i1 * 20]; p2 = &g_ph[2][i1 * 20];
                acc = 0.f;
#pragma unroll
                for (int d = 0; d < 16; d++) acc += lg2f_(p0[d] + p1[d] + p2[d]);
                g_comb[i1] = g_arr0[i1]
                           + 3.f * LN2_F * (lg2f_(p0[16] + p1[16] + p2[16]) - acc);
            }
        }
    } else {
        // ---------------- recon MAE partial (arrive, no spin) ----------------
        if (tid == 0) atomicAdd(&g_sync, 1u);
        const int rbk = b - NPAIR;
        float acc = 0.f;
        const float4* x4 = (const float4*)x;
        const float4* r4 = (const float4*)rec;
        const int n4 = (Bsz * Ff) / 4;
        for (int k = rbk * 256 + tid; k < n4; k += NRECON * 256) {
            float4 a = x4[k], bb = r4[k];
            acc += fabsf(a.x - bb.x) + fabsf(a.y - bb.y)
                 + fabsf(a.z - bb.z) + fabsf(a.w - bb.w);
        }
        sred[tid] = acc;
        __syncthreads();
#pragma unroll
        for (int o = 128; o > 0; o >>= 1) {
            if (tid < o) sred[tid] += sred[tid + o];
            __syncthreads();
        }
        if (tid == 0) g_part[rbk] = sred[0];
    }

    // ---------------- last-block final combine ----------------
    __threadfence();
    __syncthreads();
    if (tid == 0) s_tmp = atomicAdd(&g_count, 1u);
    __syncthreads();
    if (s_tmp % NGRID == NGRID - 1) {
        __threadfence();
        // total = recon_mean + mean(comb) + 45*ln(2047)
        float c = 0.f;
#pragma unroll
        for (int k = 0; k < Bsz / 256; k++)
            c += g_comb[tid + k * 256];
        float rp = (tid < NRECON) ? g_part[tid] : 0.f;

        sred[tid] = c;
        __syncthreads();
#pragma unroll
        for (int o = 128; o > 0; o >>= 1) {
            if (tid < o) sred[tid] += sred[tid + o];
            __syncthreads();
        }
        float ctot = sred[0];
        __syncthreads();
        sred[tid] = rp;
        __syncthreads();
#pragma unroll
        for (int o = 128; o > 0; o >>= 1) {
            if (tid < o) sred[tid] += sred[tid + o];
            __syncthreads();
        }
        if (tid == 0)
            out[0] = sred[0] / (float)(Bsz * Ff) + ctot / (float)Bsz
                   + 45.0f * logf(2047.0f);
    }
}

extern "C" void kernel_launch(void* const* d_in, const int* in_sizes, int n_in,
                              void* d_out, int out_size) {
    const float* x   = (const float*)d_in[0];
    const float* rec = (const float*)d_in[1];
    const float* mu  = (const float*)d_in[2];
    const float* lv  = (const float*)d_in[3];
    const float* z   = (const float*)d_in[4];
    const int*   nds = (const int*)d_in[5];
    float* out = (float*)d_out;

    k_all<<<NGRID, 256>>>(mu, lv, z, nds, x, rec, out);
}

// round 15
// speedup vs baseline: 1.8039x; 1.8039x over previous
#include <cuda_runtime.h>
#include <math_constants.h>

#define Bsz 2048
#define Dd 16
#define Ff 512
#define LOG2E_F 1.4426950408889634f
#define LN2_F 0.6931471805599453f
#define LOG2PI_F 1.8378770664093453f

#define NPAIR 256            // 128 rowgroups x 2 j-halves
#define NRECON 40            // recon blocks
#define NGRID (NPAIR + NRECON)   // 296 = 148 SM x 2 CTA: one wave

typedef unsigned long long ull;

// Coefficient store: segment s = dp*3 + type (dp=dim-pair 0..7, type a/b/c),
// each segment is float2[2048] over j: float2[j] = {coef_{2dp}[j], coef_{2dp+1}[j]}
__device__ float g_pk2f[24 * 2048 * 2];   // 393 KB (196 KB per j-half: L1D-resident)
__device__ float g_arr0[Bsz];             // log q(z|x) - log p(z)
__device__ float g_ph[2][Bsz * 20];       // per-half partials: 16 dim sums + srow (pad 20)
__device__ float g_comb[Bsz];             // arr0 + 3*ln2*(lg2 srow - sum lg2 s_d)
__device__ float g_part[NRECON];          // recon partials
__device__ unsigned g_rgc[128];           // per-rowgroup counters (monotonic, parity)
__device__ unsigned g_count;              // all-blocks counter (monotonic, mod NGRID)
__device__ unsigned g_sync;               // prep grid-barrier counter (monotonic)

__device__ __forceinline__ float ex2f(float x) {
    float y; asm("ex2.approx.ftz.f32 %0, %1;" : "=f"(y) : "f"(x)); return y;
}
__device__ __forceinline__ float lg2f_(float x) {
    float y; asm("lg2.approx.f32 %0, %1;" : "=f"(y) : "f"(x)); return y;
}
__device__ __forceinline__ ull fma2_(ull a, ull b, ull c) {
    ull d; asm("fma.rn.f32x2 %0, %1, %2, %3;" : "=l"(d) : "l"(a), "l"(b), "l"(c)); return d;
}
__device__ __forceinline__ ull add2_(ull a, ull b) {
    ull d; asm("add.rn.f32x2 %0, %1, %2;" : "=l"(d) : "l"(a), "l"(b)); return d;
}
__device__ __forceinline__ ull mul2_(ull a, ull b) {
    ull d; asm("mul.rn.f32x2 %0, %1, %2;" : "=l"(d) : "l"(a), "l"(b)); return d;
}
// exp2 of both halves of a packed f32x2, result packed
__device__ __forceinline__ ull ex2p_(ull u) {
    ull r;
    asm("{\n\t.reg .f32 l,h,a,b;\n\t"
        "mov.b64 {l,h}, %1;\n\t"
        "ex2.approx.ftz.f32 a, l;\n\t"
        "ex2.approx.ftz.f32 b, h;\n\t"
        "mov.b64 %0, {a,b};\n\t}" : "=l"(r) : "l"(u));
    return r;
}
__device__ __forceinline__ void unpk(ull v, float& lo, float& hi) {
    asm("mov.b64 {%0, %1}, %2;" : "=f"(lo), "=f"(hi) : "l"(v));
}
__device__ __forceinline__ ull pk2(float lo, float hi) {
    ull v; asm("mov.b64 %0, {%1, %2};" : "=l"(v) : "f"(lo), "f"(hi)); return v;
}

// ---------------------------------------------------------------------------
// Single persistent kernel, one wave (296 blocks x 256 threads, 2 CTAs/SM).
//  Phase 0 (pairwise blocks): prep slice (128 coeffs + 8 arr0 each), then
//    monotonic grid barrier (recon blocks arrive, don't spin).
//  Phase 1: b<256 pairwise (rowgroup x j-half). NO smem staging: the 196KB
//    half is L1D-resident; warps read coefficients with coalesced LDG.128
//    and pipeline freely (pacing sync every 4 tiles bounds drift).
//    Row accumulation via packed products (1 EX2 per element, no row EX2).
//  b>=256: recon MAE partials.
//  Per-rowgroup second finisher merges halves; last block overall -> out[0].
// ---------------------------------------------------------------------------
__global__ void __launch_bounds__(256, 2) k_all(const float* __restrict__ mu,
                                                const float* __restrict__ lv,
                                                const float* __restrict__ z,
                                                const int* __restrict__ nds,
                                                const float* __restrict__ x,
                                                const float* __restrict__ rec,
                                                float* __restrict__ out) {
    __shared__ float sred[256];
    __shared__ unsigned s_tmp;
    const int tid = threadIdx.x;
    const int lane = tid & 31;
    const int b = blockIdx.x;
    const ull ONE2 = 0x3F8000003F800000ull;       // {1.0f, 1.0f}

    if (b < NPAIR) {
        // ================= phase 0: prep slice =================
        if (tid < 128) {
            int idx = b * 128 + tid;              // 256*128 = 32768 = Bsz*Dd
            int j = idx >> 4, d = idx & 15;
            float m = mu[idx], v = lv[idx];
            float a = -0.5f * LOG2E_F * ex2f(-v * LOG2E_F);
            float off = -0.5f * LOG2E_F * (v + LOG2PI_F);
            float bb = -2.0f * a * m;
            float c = fmaf(a * m, m, off);
            if (j < 2) {
                float Nf = (float)(*nds);
                float dL0 = lg2f_(2047.0f / Nf);
                float dL1 = lg2f_((Nf - 2047.0f) / Nf);
                c += (j == 0) ? dL0 : dL1;
            }
            int dp = d >> 1, h = d & 1;
            int e = j * 2 + h;
            g_pk2f[(dp * 3 + 0) * 4096 + e] = a;
            g_pk2f[(dp * 3 + 1) * 4096 + e] = bb;
            g_pk2f[(dp * 3 + 2) * 4096 + e] = c;
        } else if (tid < 136) {
            int i = b * 8 + (tid - 128);          // 256*8 = 2048
            float acc = 0.f, sz2 = 0.f;
#pragma unroll
            for (int d = 0; d < Dd; d++) {
                float zd = z[i * Dd + d];
                float md = mu[i * Dd + d];
                float vd = lv[i * Dd + d];
                float t = zd - md;
                acc += -0.5f * (t * t * ex2f(-vd * LOG2E_F) + vd + LOG2PI_F);
                sz2 = fmaf(zd, zd, sz2);
            }
            float lprior = -0.5f * (sz2 * 0.36787944117144233f + 16.0f * (1.0f + LOG2PI_F));
            g_arr0[i] = acc - lprior;
        }
        __threadfence();
        __syncthreads();
        if (tid == 0) {
            unsigned old = atomicAdd(&g_sync, 1u);
            unsigned target = (old / NGRID + 1u) * NGRID;
            while (*(volatile unsigned*)&g_sync < target) { }
        }
        __syncthreads();
        __threadfence();

        // ================= phase 1: pairwise =================
        const int half = b >> 7;                  // 0 or 1 (j-half)
        const int rg = b & 127;                   // row-group (16 rows)
        const int w = tid >> 5;                   // 0..7
        const int i0 = rg * 16 + 2 * w, i1 = i0 + 1;

        ull zp0[8], zp1[8];
        {
            const float4* zq = (const float4*)(z + (size_t)i0 * Dd);
#pragma unroll
            for (int k = 0; k < 4; k++) {
                float4 v = zq[k];
                zp0[2 * k] = pk2(v.x, v.y); zp0[2 * k + 1] = pk2(v.z, v.w);
            }
            const float4* zq1 = (const float4*)(z + (size_t)i1 * Dd);
#pragma unroll
            for (int k = 0; k < 4; k++) {
                float4 v = zq1[k];
                zp1[2 * k] = pk2(v.x, v.y); zp1[2 * k + 1] = pk2(v.z, v.w);
            }
        }

        ull s20[8], s21[8];                       // packed per-dim sums
        float srow0 = 0.f, srow1 = 0.f;
#pragma unroll
        for (int dp = 0; dp < 8; dp++) { s20[dp] = 0ull; s21[dp] = 0ull; }

        // Direct-LDG base: lane covers j-pair (2*lane, 2*lane+1) of each tile.
        // Segment stride = 16 KB; tile stride = 512 B within a segment.
        const char* tb = (const char*)g_pk2f + (size_t)half * 8192
                       + (size_t)lane * 16;

#pragma unroll 1
        for (int t = 0; t < 16; t++) {
            const char* p = tb + (size_t)t * 512;
            ull P00 = ONE2, P01 = ONE2, P10 = ONE2, P11 = ONE2;

#pragma unroll
            for (int dp = 0; dp < 8; dp++) {
                ulonglong2 A = *(const ulonglong2*)(p + (size_t)(dp * 3 + 0) * 16384);
                ulonglong2 B = *(const ulonglong2*)(p + (size_t)(dp * 3 + 1) * 16384);
                ulonglong2 C = *(const ulonglong2*)(p + (size_t)(dp * 3 + 2) * 16384);
                ull u, e;
                u = fma2_(zp0[dp], fma2_(zp0[dp], A.x, B.x), C.x);
                e = ex2p_(u); s20[dp] = add2_(s20[dp], e); P00 = mul2_(P00, e);
                u = fma2_(zp0[dp], fma2_(zp0[dp], A.y, B.y), C.y);
                e = ex2p_(u); s20[dp] = add2_(s20[dp], e); P01 = mul2_(P01, e);
                u = fma2_(zp1[dp], fma2_(zp1[dp], A.x, B.x), C.x);
                e = ex2p_(u); s21[dp] = add2_(s21[dp], e); P10 = mul2_(P10, e);
                u = fma2_(zp1[dp], fma2_(zp1[dp], A.y, B.y), C.y);
                e = ex2p_(u); s21[dp] = add2_(s21[dp], e); P11 = mul2_(P11, e);
            }
            {   // row term = product over all 16 dims = l*h of packed product
                float l, h;
                unpk(P00, l, h); srow0 = fmaf(l, h, srow0);
                unpk(P01, l, h); srow0 = fmaf(l, h, srow0);
                unpk(P10, l, h); srow1 = fmaf(l, h, srow1);
                unpk(P11, l, h); srow1 = fmaf(l, h, srow1);
            }
            // pacing barrier: bounds intra-CTA drift so the L1D working set
            // stays a few tiles wide (no per-tile lockstep).
            if ((t & 3) == 3) __syncthreads();
        }

        // unpack packed accumulators
        float s0[16], s1[16];
#pragma unroll
        for (int dp = 0; dp < 8; dp++) {
            unpk(s20[dp], s0[2 * dp], s0[2 * dp + 1]);
            unpk(s21[dp], s1[2 * dp], s1[2 * dp + 1]);
        }

        // ---- post-loop exact corrections: j=0/1 live in half 0, lane 0 ----
        if (half == 0 && lane == 0) {
            const ulonglong2* pk = (const ulonglong2*)g_pk2f;
            float Nf = (float)(*nds);
            float dL0 = lg2f_(2047.0f / Nf);
            float dL1 = lg2f_((Nf - 2047.0f) / Nf);
            float S0_0 = 0.f, S1_0 = 0.f, S0_1 = 0.f, S1_1 = 0.f;
#pragma unroll
            for (int dp = 0; dp < 8; dp++) {
                ulonglong2 A = pk[(dp * 3 + 0) * 1024];
                ulonglong2 B = pk[(dp * 3 + 1) * 1024];
                ulonglong2 C = pk[(dp * 3 + 2) * 1024];
                float l, h;
                ull u0 = fma2_(zp0[dp], fma2_(zp0[dp], A.x, B.x), C.x);
                unpk(u0, l, h); S0_0 += l + h;
                ull u1 = fma2_(zp0[dp], fma2_(zp0[dp], A.y, B.y), C.y);
                unpk(u1, l, h); S1_0 += l + h;
                ull v0 = fma2_(zp1[dp], fma2_(zp1[dp], A.x, B.x), C.x);
                unpk(v0, l, h); S0_1 += l + h;
                ull v1 = fma2_(zp1[dp], fma2_(zp1[dp], A.y, B.y), C.y);
                unpk(v1, l, h); S1_1 += l + h;
            }
            // row-sum: loop applied 16*dL_j; true weight is 1*dL_j(row).
            float c00 = (i0 == Bsz - 2) ? (dL1 - 16.f * dL0) : (-15.f * dL0);
            float c01 = -15.f * dL0;                  // odd rows are never B-2
            float c1  = -15.f * dL1;
            srow0 += (ex2f(c00) - 1.f) * ex2f(S0_0) + (ex2f(c1) - 1.f) * ex2f(S1_0);
            srow1 += (ex2f(c01) - 1.f) * ex2f(S0_1) + (ex2f(c1) - 1.f) * ex2f(S1_1);
            // W[B-2, 0] per-dim override (row B-2 is even -> row i0): recompute u
            if (i0 == Bsz - 2) {
                float wfix = ex2f(dL1 - dL0) - 1.f;
#pragma unroll
                for (int dp = 0; dp < 8; dp++) {
                    ulonglong2 A = pk[(dp * 3 + 0) * 1024];
                    ulonglong2 B = pk[(dp * 3 + 1) * 1024];
                    ulonglong2 C = pk[(dp * 3 + 2) * 1024];
                    float l, h;
                    ull u0 = fma2_(zp0[dp], fma2_(zp0[dp], A.x, B.x), C.x);
                    unpk(u0, l, h);
                    s0[2 * dp] += wfix * ex2f(l);
                    s0[2 * dp + 1] += wfix * ex2f(h);
                }
            }
        }

        // ---- plain-sum butterfly ----
#pragma unroll
        for (int off = 16; off > 0; off >>= 1) {
#pragma unroll
            for (int d = 0; d < 16; d++) {
                s0[d] += __shfl_xor_sync(0xffffffffu, s0[d], off);
                s1[d] += __shfl_xor_sync(0xffffffffu, s1[d], off);
            }
            srow0 += __shfl_xor_sync(0xffffffffu, srow0, off);
            srow1 += __shfl_xor_sync(0xffffffffu, srow1, off);
        }

        // ---- write half partials ----
        if (lane == 0) {
            float* ph = &g_ph[half][0];
            float4* d0 = (float4*)&ph[i0 * 20];
            d0[0] = make_float4(s0[0], s0[1], s0[2], s0[3]);
            d0[1] = make_float4(s0[4], s0[5], s0[6], s0[7]);
            d0[2] = make_float4(s0[8], s0[9], s0[10], s0[11]);
            d0[3] = make_float4(s0[12], s0[13], s0[14], s0[15]);
            ph[i0 * 20 + 16] = srow0;
            float4* d1 = (float4*)&ph[i1 * 20];
            d1[0] = make_float4(s1[0], s1[1], s1[2], s1[3]);
            d1[1] = make_float4(s1[4], s1[5], s1[6], s1[7]);
            d1[2] = make_float4(s1[8], s1[9], s1[10], s1[11]);
            d1[3] = make_float4(s1[12], s1[13], s1[14], s1[15]);
            ph[i1 * 20 + 16] = srow1;
        }
        __syncthreads();
        if (tid == 0) {
            __threadfence();
            s_tmp = atomicAdd(&g_rgc[rg], 1u);
        }
        __syncthreads();
        if (s_tmp & 1u) {            // second finisher (this replay) merges
            __threadfence();
            if (lane == 0) {
                const float* o0 = &g_ph[1 - half][i0 * 20];
                float acc = 0.f;
#pragma unroll
                for (int d = 0; d < 16; d++) acc += lg2f_(s0[d] + o0[d]);
                g_comb[i0] = g_arr0[i0]
                           + 3.f * LN2_F * (lg2f_(srow0 + o0[16]) - acc);
                const float* o1 = &g_ph[1 - half][i1 * 20];
                acc = 0.f;
#pragma unroll
                for (int d = 0; d < 16; d++) acc += lg2f_(s1[d] + o1[d]);
                g_comb[i1] = g_arr0[i1]
                           + 3.f * LN2_F * (lg2f_(srow1 + o1[16]) - acc);
            }
        }
    } else {
        // ---------------- recon MAE partial (arrive, no spin) ----------------
        if (tid == 0) atomicAdd(&g_sync, 1u);
        const int rbk = b - NPAIR;
        float acc = 0.f;
        const float4* x4 = (const float4*)x;
        const float4* r4 = (const float4*)rec;
        const int n4 = (Bsz * Ff) / 4;
        for (int k = rbk * 256 + tid; k < n4; k += NRECON * 256) {
            float4 a = x4[k], bb = r4[k];
            acc += fabsf(a.x - bb.x) + fabsf(a.y - bb.y)
                 + fabsf(a.z - bb.z) + fabsf(a.w - bb.w);
        }
        sred[tid] = acc;
        __syncthreads();
#pragma unroll
        for (int o = 128; o > 0; o >>= 1) {
            if (tid < o) sred[tid] += sred[tid + o];
            __syncthreads();
        }
        if (tid == 0) g_part[rbk] = sred[0];
    }

    // ---------------- last-block final combine ----------------
    __threadfence();
    __syncthreads();
    if (tid == 0) s_tmp = atomicAdd(&g_count, 1u);
    __syncthreads();
    if (s_tmp % NGRID == NGRID - 1) {
        __threadfence();
        // total = recon_mean + mean(comb) + 45*ln(2047)
        float c = 0.f;
#pragma unroll
        for (int k = 0; k < Bsz / 256; k++)
            c += g_comb[tid + k * 256];
        float rp = (tid < NRECON) ? g_part[tid] : 0.f;

        sred[tid] = c;
        __syncthreads();
#pragma unroll
        for (int o = 128; o > 0; o >>= 1) {
            if (tid < o) sred[tid] += sred[tid + o];
            __syncthreads();
        }
        float ctot = sred[0];
        __syncthreads();
        sred[tid] = rp;
        __syncthreads();
#pragma unroll
        for (int o = 128; o > 0; o >>= 1) {
            if (tid < o) sred[tid] += sred[tid + o];
            __syncthreads();
        }
        if (tid == 0)
            out[0] = sred[0] / (float)(Bsz * Ff) + ctot / (float)Bsz
                   + 45.0f * logf(2047.0f);
    }
}

extern "C" void kernel_launch(void* const* d_in, const int* in_sizes, int n_in,
                              void* d_out, int out_size) {
    const float* x   = (const float*)d_in[0];
    const float* rec = (const float*)d_in[1];
    const float* mu  = (const float*)d_in[2];
    const float* lv  = (const float*)d_in[3];
    const float* z   = (const float*)d_in[4];
    const int*   nds = (const int*)d_in[5];
    float* out = (float*)d_out;

    k_all<<<NGRID, 256>>>(mu, lv, z, nds, x, rec, out);
}

// round 17
// speedup vs baseline: 2.0124x; 1.1156x over previous
#include <cuda_runtime.h>
#include <math_constants.h>

#define Bsz 2048
#define Dd 16
#define Ff 512
#define LOG2E_F 1.4426950408889634f
#define LN2_F 0.6931471805599453f
#define LOG2PI_F 1.8378770664093453f

#define NPAIR 384            // 128 rowgroups x 3 j-thirds
#define NRECON 60            // recon blocks
#define NGRID (NPAIR + NRECON)   // 444 = 148 SM x 3 CTA: exactly one wave

typedef unsigned long long ull;

// Coefficient store: segment s = dp*3 + type (dp=dim-pair 0..7, type a/b/c),
// each segment is float2[2048] over j: float2[j] = {coef_{2dp}[j], coef_{2dp+1}[j]}
__device__ float g_pk2f[24 * 2048 * 2];   // 393 KB
__device__ float g_arr0[Bsz];             // log q(z|x) - log p(z)
__device__ float g_ph[3][Bsz * 20];       // per-third partials: 16 dim sums + srow (pad 20)
__device__ float g_comb[Bsz];             // arr0 + 3*ln2*(lg2 srow - sum lg2 s_d)
__device__ float g_part[NRECON];          // recon partials
__device__ unsigned g_rgc[128];           // per-rowgroup counters (monotonic, mod 3)
__device__ unsigned g_count;              // all-blocks counter (monotonic, mod NGRID)
__device__ unsigned g_sync;               // prep grid-barrier counter (monotonic)

__device__ __forceinline__ float ex2f(float x) {
    float y; asm("ex2.approx.ftz.f32 %0, %1;" : "=f"(y) : "f"(x)); return y;
}
__device__ __forceinline__ float lg2f_(float x) {
    float y; asm("lg2.approx.f32 %0, %1;" : "=f"(y) : "f"(x)); return y;
}
__device__ __forceinline__ ull fma2_(ull a, ull b, ull c) {
    ull d; asm("fma.rn.f32x2 %0, %1, %2, %3;" : "=l"(d) : "l"(a), "l"(b), "l"(c)); return d;
}
__device__ __forceinline__ ull add2_(ull a, ull b) {
    ull d; asm("add.rn.f32x2 %0, %1, %2;" : "=l"(d) : "l"(a), "l"(b)); return d;
}
__device__ __forceinline__ ull mul2_(ull a, ull b) {
    ull d; asm("mul.rn.f32x2 %0, %1, %2;" : "=l"(d) : "l"(a), "l"(b)); return d;
}
// exp2 of both halves of a packed f32x2, result packed
__device__ __forceinline__ ull ex2p_(ull u) {
    ull r;
    asm("{\n\t.reg .f32 l,h,a,b;\n\t"
        "mov.b64 {l,h}, %1;\n\t"
        "ex2.approx.ftz.f32 a, l;\n\t"
        "ex2.approx.ftz.f32 b, h;\n\t"
        "mov.b64 %0, {a,b};\n\t}" : "=l"(r) : "l"(u));
    return r;
}
__device__ __forceinline__ void unpk(ull v, float& lo, float& hi) {
    asm("mov.b64 {%0, %1}, %2;" : "=f"(lo), "=f"(hi) : "l"(v));
}
__device__ __forceinline__ ull pk2(float lo, float hi) {
    ull v; asm("mov.b64 %0, {%1, %2};" : "=l"(v) : "f"(lo), "f"(hi)); return v;
}
__device__ __forceinline__ void cpa16(unsigned d, const void* s) {
    asm volatile("cp.async.cg.shared.global [%0], [%1], 16;" :: "r"(d), "l"(s));
}

// ---------------------------------------------------------------------------
// Single persistent kernel, one wave (444 blocks x 256 threads, 3 CTAs/SM).
// Same logic as the (correct) R13 kernel; the ONLY change is that the
// warp-uniform z-values live in a 1KB smem array (broadcast LDS.64 reads)
// instead of 32 registers, so the hot loop fits the 84-reg budget of
// __launch_bounds__(256,3) without spilling.
// ---------------------------------------------------------------------------
__global__ void __launch_bounds__(256, 3) k_all(const float* __restrict__ mu,
                                                const float* __restrict__ lv,
                                                const float* __restrict__ z,
                                                const int* __restrict__ nds,
                                                const float* __restrict__ x,
                                                const float* __restrict__ rec,
                                                float* __restrict__ out) {
    __shared__ float4 sbuf[3][768];               // 3 x 12 KB tiles
    __shared__ ull zsm[128];                      // [warp][row*8+dp] packed z
    __shared__ float sred[256];
    __shared__ unsigned s_tmp;
    const int tid = threadIdx.x;
    const int lane = tid & 31;
    const int b = blockIdx.x;
    const ull ONE2 = 0x3F8000003F800000ull;       // {1.0f, 1.0f}

    if (b < NPAIR) {
        // ================= phase 0: prep slice =================
        if (b < 256) {
            if (tid < 128) {
                int idx = b * 128 + tid;          // 256*128 = 32768 = Bsz*Dd
                int j = idx >> 4, d = idx & 15;
                float m = mu[idx], v = lv[idx];
                float a = -0.5f * LOG2E_F * ex2f(-v * LOG2E_F);
                float off = -0.5f * LOG2E_F * (v + LOG2PI_F);
                float bb = -2.0f * a * m;
                float c = fmaf(a * m, m, off);
                if (j < 2) {
                    float Nf = (float)(*nds);
                    float dL0 = lg2f_(2047.0f / Nf);
                    float dL1 = lg2f_((Nf - 2047.0f) / Nf);
                    c += (j == 0) ? dL0 : dL1;
                }
                int dp = d >> 1, h = d & 1;
                int e = j * 2 + h;
                g_pk2f[(dp * 3 + 0) * 4096 + e] = a;
                g_pk2f[(dp * 3 + 1) * 4096 + e] = bb;
                g_pk2f[(dp * 3 + 2) * 4096 + e] = c;
            } else if (tid < 136) {
                int i = b * 8 + (tid - 128);      // 256*8 = 2048
                float acc = 0.f, sz2 = 0.f;
#pragma unroll
                for (int d = 0; d < Dd; d++) {
                    float zd = z[i * Dd + d];
                    float md = mu[i * Dd + d];
                    float vd = lv[i * Dd + d];
                    float t = zd - md;
                    acc += -0.5f * (t * t * ex2f(-vd * LOG2E_F) + vd + LOG2PI_F);
                    sz2 = fmaf(zd, zd, sz2);
                }
                float lprior = -0.5f * (sz2 * 0.36787944117144233f + 16.0f * (1.0f + LOG2PI_F));
                g_arr0[i] = acc - lprior;
            }
        }
        __threadfence();
        __syncthreads();
        if (tid == 0) {
            unsigned old = atomicAdd(&g_sync, 1u);
            unsigned target = (old / NGRID + 1u) * NGRID;
            while (*(volatile unsigned*)&g_sync < target) { }
        }
        __syncthreads();
        __threadfence();

        // ================= phase 1: pairwise =================
        const int third = b >> 7;                 // 0,1,2 (j-third)
        const int rg = b & 127;                   // row-group (16 rows)
        const int NT = (third < 2) ? 11 : 10;     // tiles in this third
        const int toff = third * 11;              // first tile (third 2 -> 22)
        const int w = tid >> 5;                   // 0..7
        const int i0 = rg * 16 + 2 * w, i1 = i0 + 1;

        // z-values -> smem (warp-uniform per dp; broadcast reads in the loop)
        if (lane < 8) {
            zsm[w * 16 + lane] = pk2(z[i0 * Dd + 2 * lane], z[i0 * Dd + 2 * lane + 1]);
        } else if (lane < 16) {
            int dp = lane - 8;
            zsm[w * 16 + 8 + dp] = pk2(z[i1 * Dd + 2 * dp], z[i1 * Dd + 2 * dp + 1]);
        }

        ull s20[8], s21[8];                       // packed per-dim sums
        float srow0 = 0.f, srow1 = 0.f;
#pragma unroll
        for (int dp = 0; dp < 8; dp++) { s20[dp] = 0ull; s21[dp] = 0ull; }

        // single-base addressing: chunk k at +k*131072 (src) / +k*4096 (dst)
        const char* srcbase = (const char*)g_pk2f
                            + ((size_t)(tid >> 5) * 1024 + (tid & 31)) * 16
                            + (size_t)toff * 512;
        const unsigned dstb0 = (unsigned)__cvta_generic_to_shared(&sbuf[0][0])
                             + (unsigned)(((tid >> 5) * 32 + (tid & 31)) * 16);

        // prologue: stage tiles 0 and 1 of this third
#pragma unroll
        for (int k = 0; k < 3; k++) cpa16(dstb0 + k * 4096u, srcbase + (size_t)k * 131072);
        asm volatile("cp.async.commit_group;");
#pragma unroll
        for (int k = 0; k < 3; k++) cpa16(dstb0 + 12288u + k * 4096u, srcbase + 512 + (size_t)k * 131072);
        asm volatile("cp.async.commit_group;");

        int rb = 0;   // t % 3
#pragma unroll 1
        for (int t = 0; t < NT; t++) {
            asm volatile("cp.async.wait_group 1;");
            __syncthreads();

            const ulonglong2* sb2 = (const ulonglong2*)sbuf[rb];
            ull P00 = ONE2, P01 = ONE2, P10 = ONE2, P11 = ONE2;

#pragma unroll
            for (int dp = 0; dp < 8; dp++) {
                ulonglong2 A = sb2[(dp * 3 + 0) * 32 + lane];
                ulonglong2 B = sb2[(dp * 3 + 1) * 32 + lane];
                ulonglong2 C = sb2[(dp * 3 + 2) * 32 + lane];
                ull za = zsm[w * 16 + dp];        // broadcast LDS.64
                ull zb = zsm[w * 16 + 8 + dp];    // broadcast LDS.64
                ull u, e;
                u = fma2_(za, fma2_(za, A.x, B.x), C.x);
                e = ex2p_(u); s20[dp] = add2_(s20[dp], e); P00 = mul2_(P00, e);
                u = fma2_(za, fma2_(za, A.y, B.y), C.y);
                e = ex2p_(u); s20[dp] = add2_(s20[dp], e); P01 = mul2_(P01, e);
                u = fma2_(zb, fma2_(zb, A.x, B.x), C.x);
                e = ex2p_(u); s21[dp] = add2_(s21[dp], e); P10 = mul2_(P10, e);
                u = fma2_(zb, fma2_(zb, A.y, B.y), C.y);
                e = ex2p_(u); s21[dp] = add2_(s21[dp], e); P11 = mul2_(P11, e);
            }
            {   // row term = product over all 16 dims = l*h of packed product
                float l, h;
                unpk(P00, l, h); srow0 = fmaf(l, h, srow0);
                unpk(P01, l, h); srow0 = fmaf(l, h, srow0);
                unpk(P10, l, h); srow1 = fmaf(l, h, srow1);
                unpk(P11, l, h); srow1 = fmaf(l, h, srow1);
            }

            // fill tile t+2 into buf[(t+2)%3] (== buffer consumed at t-1; the
            // sync above proves all threads finished compute(t-1)).
            if (t + 2 < NT) {
                int fb = rb + 2; if (fb >= 3) fb -= 3;
                unsigned boff = (unsigned)fb * 12288u;
                const char* sp = srcbase + (size_t)(t + 2) * 512;
#pragma unroll
                for (int k = 0; k < 3; k++)
                    cpa16(dstb0 + boff + k * 4096u, sp + (size_t)k * 131072);
            }
            asm volatile("cp.async.commit_group;");
            if (++rb == 3) rb = 0;
        }

        // unpack packed accumulators
        float s0[16], s1[16];
#pragma unroll
        for (int dp = 0; dp < 8; dp++) {
            unpk(s20[dp], s0[2 * dp], s0[2 * dp + 1]);
            unpk(s21[dp], s1[2 * dp], s1[2 * dp + 1]);
        }

        // ---- post-loop exact corrections: j=0/1 live in third 0, lane 0 ----
        if (third == 0 && lane == 0) {
            const ulonglong2* pk = (const ulonglong2*)g_pk2f;
            float Nf = (float)(*nds);
            float dL0 = lg2f_(2047.0f / Nf);
            float dL1 = lg2f_((Nf - 2047.0f) / Nf);
            float S0_0 = 0.f, S1_0 = 0.f, S0_1 = 0.f, S1_1 = 0.f;
#pragma unroll
            for (int dp = 0; dp < 8; dp++) {
                ull za = zsm[w * 16 + dp];
                ull zb = zsm[w * 16 + 8 + dp];
                ulonglong2 A = pk[(dp * 3 + 0) * 1024];
                ulonglong2 B = pk[(dp * 3 + 1) * 1024];
                ulonglong2 C = pk[(dp * 3 + 2) * 1024];
                float l, h;
                ull u0 = fma2_(za, fma2_(za, A.x, B.x), C.x);
                unpk(u0, l, h); S0_0 += l + h;
                ull u1 = fma2_(za, fma2_(za, A.y, B.y), C.y);
                unpk(u1, l, h); S1_0 += l + h;
                ull v0 = fma2_(zb, fma2_(zb, A.x, B.x), C.x);
                unpk(v0, l, h); S0_1 += l + h;
                ull v1 = fma2_(zb, fma2_(zb, A.y, B.y), C.y);
                unpk(v1, l, h); S1_1 += l + h;
            }
            // row-sum: loop applied 16*dL_j; true weight is 1*dL_j(row).
            float c00 = (i0 == Bsz - 2) ? (dL1 - 16.f * dL0) : (-15.f * dL0);
            float c01 = -15.f * dL0;                  // odd rows are never B-2
            float c1  = -15.f * dL1;
            srow0 += (ex2f(c00) - 1.f) * ex2f(S0_0) + (ex2f(c1) - 1.f) * ex2f(S1_0);
            srow1 += (ex2f(c01) - 1.f) * ex2f(S0_1) + (ex2f(c1) - 1.f) * ex2f(S1_1);
            // W[B-2, 0] per-dim override (row B-2 is even -> row i0): recompute u
            if (i0 == Bsz - 2) {
                float wfix = ex2f(dL1 - dL0) - 1.f;
#pragma unroll
                for (int dp = 0; dp < 8; dp++) {
                    ull za = zsm[w * 16 + dp];
                    ulonglong2 A = pk[(dp * 3 + 0) * 1024];
                    ulonglong2 B = pk[(dp * 3 + 1) * 1024];
                    ulonglong2 C = pk[(dp * 3 + 2) * 1024];
                    float l, h;
                    ull u0 = fma2_(za, fma2_(za, A.x, B.x), C.x);
                    unpk(u0, l, h);
                    s0[2 * dp] += wfix * ex2f(l);
                    s0[2 * dp + 1] += wfix * ex2f(h);
                }
            }
        }

        // ---- plain-sum butterfly ----
#pragma unroll
        for (int off = 16; off > 0; off >>= 1) {
#pragma unroll
            for (int d = 0; d < 16; d++) {
                s0[d] += __shfl_xor_sync(0xffffffffu, s0[d], off);
                s1[d] += __shfl_xor_sync(0xffffffffu, s1[d], off);
            }
            srow0 += __shfl_xor_sync(0xffffffffu, srow0, off);
            srow1 += __shfl_xor_sync(0xffffffffu, srow1, off);
        }

        // ---- write third partials ----
        if (lane == 0) {
            float* ph = &g_ph[third][0];
            float4* d0 = (float4*)&ph[i0 * 20];
            d0[0] = make_float4(s0[0], s0[1], s0[2], s0[3]);
            d0[1] = make_float4(s0[4], s0[5], s0[6], s0[7]);
            d0[2] = make_float4(s0[8], s0[9], s0[10], s0[11]);
            d0[3] = make_float4(s0[12], s0[13], s0[14], s0[15]);
            ph[i0 * 20 + 16] = srow0;
            float4* d1 = (float4*)&ph[i1 * 20];
            d1[0] = make_float4(s1[0], s1[1], s1[2], s1[3]);
            d1[1] = make_float4(s1[4], s1[5], s1[6], s1[7]);
            d1[2] = make_float4(s1[8], s1[9], s1[10], s1[11]);
            d1[3] = make_float4(s1[12], s1[13], s1[14], s1[15]);
            ph[i1 * 20 + 16] = srow1;
        }
        __syncthreads();
        if (tid == 0) {
            __threadfence();
            s_tmp = atomicAdd(&g_rgc[rg], 1u);
        }
        __syncthreads();
        if (s_tmp % 3u == 2u) {      // last finisher of this rowgroup merges
            __threadfence();
            if (lane == 0) {
                const float* p0 = &g_ph[0][i0 * 20];
                const float* p1 = &g_ph[1][i0 * 20];
                const float* p2 = &g_ph[2][i0 * 20];
                float acc = 0.f;
#pragma unroll
                for (int d = 0; d < 16; d++) acc += lg2f_(p0[d] + p1[d] + p2[d]);
                g_comb[i0] = g_arr0[i0]
                           + 3.f * LN2_F * (lg2f_(p0[16] + p1[16] + p2[16]) - acc);
                p0 = &g_ph[0][i1 * 20]; p1 = &g_ph[1][i1 * 20]; p2 = &g_ph[2][i1 * 20];
                acc = 0.f;
#pragma unroll
                for (int d = 0; d < 16; d++) acc += lg2f_(p0[d] + p1[d] + p2[d]);
                g_comb[i1] = g_arr0[i1]
                           + 3.f * LN2_F * (lg2f_(p0[16] + p1[16] + p2[16]) - acc);
            }
        }
    } else {
        // ---------------- recon MAE partial (arrive, no spin) ----------------
        if (tid == 0) atomicAdd(&g_sync, 1u);
        const int rbk = b - NPAIR;
        float acc = 0.f;
        const float4* x4 = (const float4*)x;
        const float4* r4 = (const float4*)rec;
        const int n4 = (Bsz * Ff) / 4;
        for (int k = rbk * 256 + tid; k < n4; k += NRECON * 256) {
            float4 a = x4[k], bb = r4[k];
            acc += fabsf(a.x - bb.x) + fabsf(a.y - bb.y)
                 + fabsf(a.z - bb.z) + fabsf(a.w - bb.w);
        }
        sred[tid] = acc;
        __syncthreads();
#pragma unroll
        for (int o = 128; o > 0; o >>= 1) {
            if (tid < o) sred[tid] += sred[tid + o];
            __syncthreads();
        }
        if (tid == 0) g_part[rbk] = sred[0];
    }

    // ---------------- last-block final combine ----------------
    __threadfence();
    __syncthreads();
    if (tid == 0) s_tmp = atomicAdd(&g_count, 1u);
    __syncthreads();
    if (s_tmp % NGRID == NGRID - 1) {
        __threadfence();
        // total = recon_mean + mean(comb) + 45*ln(2047)
        float c = 0.f;
#pragma unroll
        for (int k = 0; k < Bsz / 256; k++)
            c += g_comb[tid + k * 256];
        float rp = (tid < NRECON) ? g_part[tid] : 0.f;

        sred[tid] = c;
        __syncthreads();
#pragma unroll
        for (int o = 128; o > 0; o >>= 1) {
            if (tid < o) sred[tid] += sred[tid + o];
            __syncthreads();
        }
        float ctot = sred[0];
        __syncthreads();
        sred[tid] = rp;
        __syncthreads();
#pragma unroll
        for (int o = 128; o > 0; o >>= 1) {
            if (tid < o) sred[tid] += sred[tid + o];
            __syncthreads();
        }
        if (tid == 0)
            out[0] = sred[0] / (float)(Bsz * Ff) + ctot / (float)Bsz
                   + 45.0f * logf(2047.0f);
    }
}

extern "C" void kernel_launch(void* const* d_in, const int* in_sizes, int n_in,
                              void* d_out, int out_size) {
    const float* x   = (const float*)d_in[0];
    const float* rec = (const float*)d_in[1];
    const float* mu  = (const float*)d_in[2];
    const float* lv  = (const float*)d_in[3];
    const float* z   = (const float*)d_in[4];
    const int*   nds = (const int*)d_in[5];
    float* out = (float*)d_out;

    k_all<<<NGRID, 256>>>(mu, lv, z, nds, x, rec, out);
}